// round 6
// baseline (speedup 1.0000x reference)
#include <cuda_runtime.h>
#include <cstdint>

// ---------------- problem constants ----------------
constexpr int B_  = 4;
constexpr int S_  = 1024;
constexpr int E_  = 1024;
constexpr int H_  = 16;
constexpr int HD_ = 64;
constexpr int NE_ = 8;
constexpr int FF_ = 4096;
constexpr int T_  = B_ * S_;   // 4096 tokens
constexpr int NFF_ = NE_ * FF_; // 32768

// ---------------- device scratch ----------------
__device__ float g_q  [(size_t)B_ * H_ * S_ * HD_];
__device__ float g_k  [(size_t)B_ * H_ * S_ * HD_];
__device__ float g_v  [(size_t)B_ * H_ * S_ * HD_];
__device__ float g_cat[(size_t)T_ * E_];
__device__ float g_pre1[(size_t)T_ * E_];             // proj+resid, later MoE accumulator
__device__ float g_h  [(size_t)T_ * E_];              // LN1 output (tf32-rounded)
__device__ float g_probs[(size_t)T_ * NE_];
__device__ float g_moe[(size_t)T_ * E_];              // x + sum_n probs*b2
__device__ float g_w1t[(size_t)NFF_ * E_];            // [32768,1024] K-major
__device__ float g_w2t[(size_t)E_ * NFF_];            // [1024,32768] K-major
__device__ float g_mid[(size_t)T_ * FF_];             // ONE expert's mid (64MB, L2-hot)

// ---------------- helpers ----------------
__device__ __forceinline__ float rna_tf32(float x) {
    uint32_t u;
    asm("cvt.rna.tf32.f32 %0, %1;" : "=r"(u) : "f"(x));
    return __uint_as_float(u);
}
#define CP_ASYNC16(dst, src) \
    asm volatile("cp.async.cg.shared.global [%0], [%1], 16;" :: "r"(dst), "l"(src) : "memory")
#define CP_COMMIT() asm volatile("cp.async.commit_group;" ::: "memory")
#define CP_WAIT2()  asm volatile("cp.async.wait_group 2;" ::: "memory")

__device__ __forceinline__ uint32_t smem_u32(const void* p) {
    uint32_t a;
    asm("{ .reg .u64 t; cvta.to.shared.u64 t, %1; cvt.u32.u64 %0, t; }"
        : "=r"(a) : "l"(p));
    return a;
}

__device__ __forceinline__ void mma_tf32(float* c, const uint32_t* a, const uint32_t* b) {
    asm volatile(
        "mma.sync.aligned.m16n8k8.row.col.f32.tf32.tf32.f32 "
        "{%0,%1,%2,%3}, {%4,%5,%6,%7}, {%8,%9}, {%0,%1,%2,%3};"
        : "+f"(c[0]), "+f"(c[1]), "+f"(c[2]), "+f"(c[3])
        : "r"(a[0]), "r"(a[1]), "r"(a[2]), "r"(a[3]), "r"(b[0]), "r"(b[1]));
}

// =====================================================================
// tf32 mma.sync GEMM: D[M,N] = A[M,K] @ B[N,:K]^T.
// A K-major stride K; B rows stride ldb (>= K).
// CTA 128x128, 8 warps (2x4), warp tile 64x32 (4x4 m16n8k8), BK=16,
// 4-stage cp.async pipeline.
// MODE 1: C = rna(relu(acc + bias[col]) * probs[row, expert])   (expert w1)
// MODE 2: C = acc + base[row,col]   (base may alias C)           (expert w2)
// =====================================================================
constexpr int MM_LDA = 20;                    // padded row stride (words)
constexpr int MM_STAGE_W = 128 * MM_LDA;      // words per A (or B) stage
constexpr int MM_STG = 4;
constexpr int MM_SMEM = MM_STG * 2 * MM_STAGE_W * 4;  // 81920 bytes

template<int MODE>
__global__ __launch_bounds__(256, 1) void mm_gemm(
    const float* __restrict__ A, const float* __restrict__ Bm, float* __restrict__ C,
    int K, int ldb, const float* __restrict__ bias, const float* __restrict__ probs,
    const float* __restrict__ base, int expert)
{
    extern __shared__ __align__(16) float sm[];
    const uint32_t sbase = smem_u32(sm);
    const int tid = threadIdx.x, wid = tid >> 5, lane = tid & 31;
    const int row0 = blockIdx.y * 128, col0 = blockIdx.x * 128;
    const int ldC = gridDim.x * 128;
    const int wm = wid & 1, wn = wid >> 1;       // warp tile: rows wm*64, cols wn*32
    const int nch = K >> 4;

    // per-thread load slots: 2 A chunks + 2 B chunks (16B each) per stage
    const float* gA[2]; const float* gB[2];
    uint32_t oA[2], oB[2];
    #pragma unroll
    for (int i = 0; i < 2; i++) {
        int c = tid * 2 + i;           // 0..511
        int r = c >> 2, kc = c & 3;    // row 0..127, k-chunk 0..3
        gA[i] = A  + (size_t)(row0 + r) * K + kc * 4;
        gB[i] = Bm + (size_t)(col0 + r) * ldb + kc * 4;
        oA[i] = (r * MM_LDA + kc * 4) * 4;
        oB[i] = (MM_STAGE_W + r * MM_LDA + kc * 4) * 4;
    }

    float acc[4][4][4] = {};

    // prefetch stages 0..2
    #pragma unroll
    for (int c = 0; c < MM_STG - 1; c++) {
        uint32_t so = sbase + c * 2 * MM_STAGE_W * 4;
        int ko = c * 16;
        CP_ASYNC16(so + oA[0], gA[0] + ko);
        CP_ASYNC16(so + oA[1], gA[1] + ko);
        CP_ASYNC16(so + oB[0], gB[0] + ko);
        CP_ASYNC16(so + oB[1], gB[1] + ko);
        CP_COMMIT();
    }

    const int lr = lane >> 2, lc = lane & 3;
    for (int c = 0; c < nch; c++) {
        CP_WAIT2();
        __syncthreads();
        // issue loads for stage c+3 (overwrites stage used by chunk c-1)
        if (c + MM_STG - 1 < nch) {
            int s = (c + MM_STG - 1) & (MM_STG - 1);
            uint32_t so = sbase + s * 2 * MM_STAGE_W * 4;
            int ko = (c + MM_STG - 1) * 16;
            CP_ASYNC16(so + oA[0], gA[0] + ko);
            CP_ASYNC16(so + oA[1], gA[1] + ko);
            CP_ASYNC16(so + oB[0], gB[0] + ko);
            CP_ASYNC16(so + oB[1], gB[1] + ko);
        }
        CP_COMMIT();

        const uint32_t* Ast = (const uint32_t*)(sm + (c & (MM_STG - 1)) * 2 * MM_STAGE_W);
        const uint32_t* Bst = Ast + MM_STAGE_W;
        #pragma unroll
        for (int kk = 0; kk < 16; kk += 8) {
            uint32_t af[4][4], bf[4][2];
            #pragma unroll
            for (int mt = 0; mt < 4; mt++) {
                int ba = (wm * 64 + mt * 16 + lr) * MM_LDA + kk + lc;
                af[mt][0] = Ast[ba];
                af[mt][1] = Ast[ba + 8 * MM_LDA];
                af[mt][2] = Ast[ba + 4];
                af[mt][3] = Ast[ba + 8 * MM_LDA + 4];
            }
            #pragma unroll
            for (int nt = 0; nt < 4; nt++) {
                int bb = (wn * 32 + nt * 8 + lr) * MM_LDA + kk + lc;
                bf[nt][0] = Bst[bb];
                bf[nt][1] = Bst[bb + 4];
            }
            #pragma unroll
            for (int mt = 0; mt < 4; mt++)
                #pragma unroll
                for (int nt = 0; nt < 4; nt++)
                    mma_tf32(acc[mt][nt], af[mt], bf[nt]);
        }
    }

    // epilogue: c0,c1 -> (row, col..col+1), c2,c3 -> (row+8, ...)
    #pragma unroll
    for (int mt = 0; mt < 4; mt++) {
        int r1 = row0 + wm * 64 + mt * 16 + lr;
        int r2 = r1 + 8;
        float p1 = 0.f, p2 = 0.f;
        if (MODE == 1) {
            p1 = probs[(size_t)r1 * NE_ + expert];
            p2 = probs[(size_t)r2 * NE_ + expert];
        }
        #pragma unroll
        for (int nt = 0; nt < 4; nt++) {
            int cg = col0 + wn * 32 + nt * 8 + lc * 2;
            if (MODE == 1) {
                float b0 = bias[cg], b1 = bias[cg + 1];
                float2 v1, v2;
                v1.x = rna_tf32(fmaxf(acc[mt][nt][0] + b0, 0.f) * p1);
                v1.y = rna_tf32(fmaxf(acc[mt][nt][1] + b1, 0.f) * p1);
                v2.x = rna_tf32(fmaxf(acc[mt][nt][2] + b0, 0.f) * p2);
                v2.y = rna_tf32(fmaxf(acc[mt][nt][3] + b1, 0.f) * p2);
                *(float2*)&C[(size_t)r1 * ldC + cg] = v1;
                *(float2*)&C[(size_t)r2 * ldC + cg] = v2;
            } else {
                float2 a1 = *(const float2*)&base[(size_t)r1 * ldC + cg];
                float2 a2 = *(const float2*)&base[(size_t)r2 * ldC + cg];
                float2 v1 = make_float2(acc[mt][nt][0] + a1.x, acc[mt][nt][1] + a1.y);
                float2 v2 = make_float2(acc[mt][nt][2] + a2.x, acc[mt][nt][3] + a2.y);
                *(float2*)&C[(size_t)r1 * ldC + cg] = v1;
                *(float2*)&C[(size_t)r2 * ldC + cg] = v2;
            }
        }
    }
}

// ---------------- transpose + tf32-round weights ----------------
__global__ __launch_bounds__(256) void transpose_rna(
    const float* __restrict__ src, float* __restrict__ dst,
    int srcStride, long dstStride, long srcExp, long dstExp)
{
    __shared__ float t[32][33];
    src += (size_t)blockIdx.z * srcExp;
    dst += (size_t)blockIdx.z * dstExp;
    const int r0 = blockIdx.y * 32, c0 = blockIdx.x * 32;
    const int tx = threadIdx.x, ty = threadIdx.y;
    #pragma unroll
    for (int i = 0; i < 4; i++)
        t[ty + i * 8][tx] = src[(size_t)(r0 + ty + i * 8) * srcStride + c0 + tx];
    __syncthreads();
    #pragma unroll
    for (int i = 0; i < 4; i++)
        dst[(size_t)(c0 + ty + i * 8) * dstStride + (r0 + tx)] = rna_tf32(t[tx][ty + i * 8]);
}

// =====================================================================
// QKV projection (fp32)
// =====================================================================
__global__ __launch_bounds__(256) void qkv_kernel(
    const float* __restrict__ x,
    const float* __restrict__ wq, const float* __restrict__ bq,
    const float* __restrict__ wk, const float* __restrict__ bk,
    const float* __restrict__ wv, const float* __restrict__ bv)
{
    __shared__ float xs[16][68];
    __shared__ float ws[3][16][64];
    const int h  = blockIdx.y;
    const int t0 = blockIdx.x * 64;
    const int tid = threadIdx.x;
    const int tx = tid & 15, ty = tid >> 4;

    float acc[3][4][4] = {};
    const int xr = tid >> 2, xc = (tid & 3) * 4;
    const int wrow = tid >> 4, wcol = (tid & 15) * 4;
    const float* wqh = wq + (size_t)h * E_ * HD_;
    const float* wkh = wk + (size_t)h * E_ * HD_;
    const float* wvh = wv + (size_t)h * E_ * HD_;

    for (int k0 = 0; k0 < E_; k0 += 16) {
        float4 xv = *(const float4*)&x[(size_t)(t0 + xr) * E_ + k0 + xc];
        float4 q4 = *(const float4*)&wqh[(size_t)(k0 + wrow) * HD_ + wcol];
        float4 k4 = *(const float4*)&wkh[(size_t)(k0 + wrow) * HD_ + wcol];
        float4 v4 = *(const float4*)&wvh[(size_t)(k0 + wrow) * HD_ + wcol];
        __syncthreads();
        xs[xc + 0][xr] = xv.x; xs[xc + 1][xr] = xv.y;
        xs[xc + 2][xr] = xv.z; xs[xc + 3][xr] = xv.w;
        *(float4*)&ws[0][wrow][wcol] = q4;
        *(float4*)&ws[1][wrow][wcol] = k4;
        *(float4*)&ws[2][wrow][wcol] = v4;
        __syncthreads();
        #pragma unroll
        for (int kk = 0; kk < 16; kk++) {
            float4 a4 = *(const float4*)&xs[kk][ty * 4];
            float a[4] = {a4.x, a4.y, a4.z, a4.w};
            float4 qb4 = *(const float4*)&ws[0][kk][tx * 4];
            float4 kb4 = *(const float4*)&ws[1][kk][tx * 4];
            float4 vb4 = *(const float4*)&ws[2][kk][tx * 4];
            float qv[4] = {qb4.x, qb4.y, qb4.z, qb4.w};
            float kv[4] = {kb4.x, kb4.y, kb4.z, kb4.w};
            float vv[4] = {vb4.x, vb4.y, vb4.z, vb4.w};
            #pragma unroll
            for (int i = 0; i < 4; i++)
                #pragma unroll
                for (int j = 0; j < 4; j++) {
                    acc[0][i][j] += a[i] * qv[j];
                    acc[1][i][j] += a[i] * kv[j];
                    acc[2][i][j] += a[i] * vv[j];
                }
        }
    }
    #pragma unroll
    for (int i = 0; i < 4; i++) {
        int t = t0 + ty * 4 + i;
        int b = t / S_, s = t % S_;
        size_t bs = ((size_t)(b * H_ + h) * S_ + s) * HD_;
        #pragma unroll
        for (int j = 0; j < 4; j++) {
            int d = tx * 4 + j;
            g_q[bs + d] = acc[0][i][j] + bq[h * HD_ + d];
            g_k[bs + d] = acc[1][i][j] + bk[h * HD_ + d];
            g_v[bs + d] = acc[2][i][j] + bv[h * HD_ + d];
        }
    }
}

// =====================================================================
// flash attention (fp32)
// =====================================================================
constexpr int AP = 68;
constexpr int ATTN_SMEM = 4 * 64 * AP * 4;

__global__ __launch_bounds__(256) void attn_kernel()
{
    extern __shared__ float asmem[];
    float* qs = asmem;
    float* ks = asmem + 64 * AP;
    float* vs = asmem + 2 * 64 * AP;
    float* ps = asmem + 3 * 64 * AP;

    const int qb = blockIdx.x;
    const int bh = blockIdx.y;
    const int b = bh / H_, h = bh % H_;
    const int q0 = qb * 64;
    const float* Q = g_q + (size_t)bh * S_ * HD_;
    const float* K = g_k + (size_t)bh * S_ * HD_;
    const float* V = g_v + (size_t)bh * S_ * HD_;

    const int tid = threadIdx.x;
    const int tx = tid & 15, ty = tid >> 4;
    const int lr = tid >> 2, lc = (tid & 3) * 16;

    #pragma unroll
    for (int ii = 0; ii < 4; ii++) {
        float4 qv = *(const float4*)&Q[(size_t)(q0 + lr) * HD_ + lc + ii * 4];
        *(float4*)&qs[lr * AP + lc + ii * 4] = qv;
    }

    float o[4][4] = {};
    float m[4], l[4];
    #pragma unroll
    for (int i = 0; i < 4; i++) { m[i] = -1e30f; l[i] = 0.f; }

    for (int jb = 0; jb <= qb; jb++) {
        const int kv0 = jb * 64;
        float4 kl[4], vl[4];
        #pragma unroll
        for (int ii = 0; ii < 4; ii++) {
            kl[ii] = *(const float4*)&K[(size_t)(kv0 + lr) * HD_ + lc + ii * 4];
            vl[ii] = *(const float4*)&V[(size_t)(kv0 + lr) * HD_ + lc + ii * 4];
        }
        __syncthreads();
        #pragma unroll
        for (int ii = 0; ii < 4; ii++) {
            *(float4*)&ks[lr * AP + lc + ii * 4] = kl[ii];
            *(float4*)&vs[lr * AP + lc + ii * 4] = vl[ii];
        }
        __syncthreads();

        float s[4][4] = {};
        #pragma unroll
        for (int d = 0; d < 64; d += 4) {
            float4 a4[4], b4[4];
            #pragma unroll
            for (int i = 0; i < 4; i++)
                a4[i] = *(const float4*)&qs[(ty * 4 + i) * AP + d];
            #pragma unroll
            for (int j = 0; j < 4; j++)
                b4[j] = *(const float4*)&ks[(tx * 4 + j) * AP + d];
            #pragma unroll
            for (int i = 0; i < 4; i++)
                #pragma unroll
                for (int j = 0; j < 4; j++)
                    s[i][j] += a4[i].x * b4[j].x + a4[i].y * b4[j].y
                             + a4[i].z * b4[j].z + a4[i].w * b4[j].w;
        }
        #pragma unroll
        for (int i = 0; i < 4; i++)
            #pragma unroll
            for (int j = 0; j < 4; j++) {
                s[i][j] *= 0.125f;
                if (kv0 + tx * 4 + j > q0 + ty * 4 + i) s[i][j] = -1e30f;
            }

        float corr[4];
        #pragma unroll
        for (int i = 0; i < 4; i++) {
            float mloc = fmaxf(fmaxf(s[i][0], s[i][1]), fmaxf(s[i][2], s[i][3]));
            #pragma unroll
            for (int off = 8; off; off >>= 1)
                mloc = fmaxf(mloc, __shfl_xor_sync(0xffffffffu, mloc, off));
            float mnew = fmaxf(m[i], mloc);
            corr[i] = __expf(fmaxf(m[i] - mnew, -87.f));
            float4 p;
            p.x = __expf(fmaxf(s[i][0] - mnew, -87.f));
            p.y = __expf(fmaxf(s[i][1] - mnew, -87.f));
            p.z = __expf(fmaxf(s[i][2] - mnew, -87.f));
            p.w = __expf(fmaxf(s[i][3] - mnew, -87.f));
            *(float4*)&ps[(ty * 4 + i) * AP + tx * 4] = p;
            float psum = p.x + p.y + p.z + p.w;
            #pragma unroll
            for (int off = 8; off; off >>= 1)
                psum += __shfl_xor_sync(0xffffffffu, psum, off);
            l[i] = l[i] * corr[i] + psum;
            m[i] = mnew;
        }
        __syncwarp();

        #pragma unroll
        for (int i = 0; i < 4; i++)
            #pragma unroll
            for (int j = 0; j < 4; j++)
                o[i][j] *= corr[i];
        #pragma unroll
        for (int c = 0; c < 64; c += 4) {
            float4 p4[4], v4[4];
            #pragma unroll
            for (int i = 0; i < 4; i++)
                p4[i] = *(const float4*)&ps[(ty * 4 + i) * AP + c];
            #pragma unroll
            for (int cc = 0; cc < 4; cc++)
                v4[cc] = *(const float4*)&vs[(c + cc) * AP + tx * 4];
            #pragma unroll
            for (int i = 0; i < 4; i++) {
                o[i][0] += p4[i].x * v4[0].x + p4[i].y * v4[1].x + p4[i].z * v4[2].x + p4[i].w * v4[3].x;
                o[i][1] += p4[i].x * v4[0].y + p4[i].y * v4[1].y + p4[i].z * v4[2].y + p4[i].w * v4[3].y;
                o[i][2] += p4[i].x * v4[0].z + p4[i].y * v4[1].z + p4[i].z * v4[2].z + p4[i].w * v4[3].z;
                o[i][3] += p4[i].x * v4[0].w + p4[i].y * v4[1].w + p4[i].z * v4[2].w + p4[i].w * v4[3].w;
            }
        }
    }
    #pragma unroll
    for (int i = 0; i < 4; i++) {
        float inv = 1.f / l[i];
        int srow = q0 + ty * 4 + i;
        float4 ov = make_float4(o[i][0] * inv, o[i][1] * inv, o[i][2] * inv, o[i][3] * inv);
        *(float4*)&g_cat[((size_t)b * S_ + srow) * E_ + h * HD_ + tx * 4] = ov;
    }
}

// =====================================================================
// fp32 SGEMM — attention projection: C = A@B + bias[col] + resid[row,col]
// =====================================================================
__global__ __launch_bounds__(256) void proj_kernel(
    const float* __restrict__ A, const float* __restrict__ Bm,
    float* __restrict__ C, int M, int N, int K,
    const float* __restrict__ bias, const float* __restrict__ resid)
{
    __shared__ float As[8][128];
    __shared__ float Bs[8][128];
    const int tid = threadIdx.x;
    const int tx = tid & 15, ty = tid >> 4;
    const int row0 = blockIdx.y * 128, col0 = blockIdx.x * 128;

    float acc[8][8] = {};
    const int arow = tid >> 1, acol = (tid & 1) * 4;
    const int brow = tid >> 5, bcol = (tid & 31) * 4;

    for (int k0 = 0; k0 < K; k0 += 8) {
        float4 av = *(const float4*)&A[(size_t)(row0 + arow) * K + k0 + acol];
        float4 bv = *(const float4*)&Bm[(size_t)(k0 + brow) * N + col0 + bcol];
        __syncthreads();
        As[acol + 0][arow] = av.x; As[acol + 1][arow] = av.y;
        As[acol + 2][arow] = av.z; As[acol + 3][arow] = av.w;
        *(float4*)&Bs[brow][bcol] = bv;
        __syncthreads();
        #pragma unroll
        for (int kk = 0; kk < 8; kk++) {
            float4 a0 = *(const float4*)&As[kk][ty * 4];
            float4 a1 = *(const float4*)&As[kk][64 + ty * 4];
            float4 b0 = *(const float4*)&Bs[kk][tx * 4];
            float4 b1 = *(const float4*)&Bs[kk][64 + tx * 4];
            float ar[8] = {a0.x, a0.y, a0.z, a0.w, a1.x, a1.y, a1.z, a1.w};
            float br_[8] = {b0.x, b0.y, b0.z, b0.w, b1.x, b1.y, b1.z, b1.w};
            #pragma unroll
            for (int i = 0; i < 8; i++)
                #pragma unroll
                for (int j = 0; j < 8; j++)
                    acc[i][j] += ar[i] * br_[j];
        }
    }
    #pragma unroll
    for (int i = 0; i < 8; i++) {
        int row = row0 + (i < 4 ? ty * 4 + i : 64 + ty * 4 + (i - 4));
        #pragma unroll
        for (int j = 0; j < 8; j++) {
            int col = col0 + (j < 4 ? tx * 4 + j : 64 + tx * 4 + (j - 4));
            size_t ci = (size_t)row * N + col;
            C[ci] = acc[i][j] + bias[col] + resid[ci];
        }
    }
}

// =====================================================================
// LayerNorm. FIRST: writes rna(h), router probs, and residual base
// g_moe = x + sum_n probs[n]*b2[n]
// =====================================================================
template<bool FIRST>
__global__ __launch_bounds__(256) void ln_kernel(
    const float* __restrict__ src, const float* __restrict__ gamma,
    const float* __restrict__ beta, float* __restrict__ dst,
    const float* __restrict__ x, const float* __restrict__ wr,
    const float* __restrict__ br, const float* __restrict__ b2)
{
    const int t = blockIdx.x, tid = threadIdx.x;
    const size_t rb = (size_t)t * E_;
    float4 v = *(const float4*)&src[rb + tid * 4];
    float sum = v.x + v.y + v.z + v.w;
    float sq  = v.x * v.x + v.y * v.y + v.z * v.z + v.w * v.w;

    __shared__ float red[16];
    const int lane = tid & 31, w = tid >> 5;
    #pragma unroll
    for (int off = 16; off; off >>= 1) {
        sum += __shfl_down_sync(0xffffffffu, sum, off);
        sq  += __shfl_down_sync(0xffffffffu, sq, off);
    }
    if (lane == 0) { red[w] = sum; red[8 + w] = sq; }
    __syncthreads();
    if (tid == 0) {
        float S = 0.f, Q = 0.f;
        for (int i = 0; i < 8; i++) { S += red[i]; Q += red[8 + i]; }
        float mean = S * (1.f / E_);
        float var  = Q * (1.f / E_) - mean * mean;
        red[0] = mean; red[1] = rsqrtf(var + 1e-5f);
    }
    __syncthreads();
    float mean = red[0], inv = red[1];

    float hv[4];
    hv[0] = (v.x - mean) * inv * gamma[tid * 4 + 0] + beta[tid * 4 + 0];
    hv[1] = (v.y - mean) * inv * gamma[tid * 4 + 1] + beta[tid * 4 + 1];
    hv[2] = (v.z - mean) * inv * gamma[tid * 4 + 2] + beta[tid * 4 + 2];
    hv[3] = (v.w - mean) * inv * gamma[tid * 4 + 3] + beta[tid * 4 + 3];
    if (FIRST) {
        *(float4*)&dst[rb + tid * 4] = make_float4(
            rna_tf32(hv[0]), rna_tf32(hv[1]), rna_tf32(hv[2]), rna_tf32(hv[3]));
    } else {
        *(float4*)&dst[rb + tid * 4] = make_float4(hv[0], hv[1], hv[2], hv[3]);
    }

    if (FIRST) {
        __shared__ float slog[8];
        float lg[8] = {};
        #pragma unroll
        for (int i = 0; i < 4; i++) {
            int e = tid * 4 + i;
            #pragma unroll
            for (int n = 0; n < 8; n++) lg[n] += hv[i] * wr[e * 8 + n];
        }
        if (tid < 8) slog[tid] = 0.f;
        __syncthreads();
        #pragma unroll
        for (int n = 0; n < 8; n++) {
            float vv = lg[n];
            #pragma unroll
            for (int off = 16; off; off >>= 1)
                vv += __shfl_down_sync(0xffffffffu, vv, off);
            if (lane == 0) atomicAdd(&slog[n], vv);
        }
        __syncthreads();
        if (tid == 0) {
            float lgf[8], mx = -1e30f;
            for (int n = 0; n < 8; n++) { lgf[n] = slog[n] + br[n]; mx = fmaxf(mx, lgf[n]); }
            float sme = 0.f, ee[8];
            for (int n = 0; n < 8; n++) { ee[n] = __expf(lgf[n] - mx); sme += ee[n]; }
            float is = 1.f / sme;
            for (int n = 0; n < 8; n++) {
                float p = ee[n] * is;
                g_probs[(size_t)t * 8 + n] = p;
                slog[n] = p;
            }
        }
        __syncthreads();
        float4 xv = *(const float4*)&x[rb + tid * 4];
        float bb[4] = {xv.x, xv.y, xv.z, xv.w};
        #pragma unroll
        for (int n = 0; n < 8; n++) {
            float p = slog[n];
            #pragma unroll
            for (int i = 0; i < 4; i++)
                bb[i] += p * b2[n * E_ + tid * 4 + i];
        }
        *(float4*)&g_moe[rb + tid * 4] = make_float4(bb[0], bb[1], bb[2], bb[3]);
    }
}

// =====================================================================
// host launcher
// =====================================================================
extern "C" void kernel_launch(void* const* d_in, const int* in_sizes, int n_in,
                              void* d_out, int out_size)
{
    const float* x    = (const float*)d_in[0];
    const float* wq   = (const float*)d_in[1];
    const float* bq   = (const float*)d_in[2];
    const float* wk   = (const float*)d_in[3];
    const float* bk   = (const float*)d_in[4];
    const float* wv   = (const float*)d_in[5];
    const float* bv   = (const float*)d_in[6];
    const float* wp   = (const float*)d_in[7];
    const float* bp   = (const float*)d_in[8];
    const float* ln1g = (const float*)d_in[9];
    const float* ln1b = (const float*)d_in[10];
    const float* ln2g = (const float*)d_in[11];
    const float* ln2b = (const float*)d_in[12];
    const float* wr   = (const float*)d_in[13];
    const float* br   = (const float*)d_in[14];
    const float* w1   = (const float*)d_in[15];
    const float* b1   = (const float*)d_in[16];
    const float* w2   = (const float*)d_in[17];
    const float* b2   = (const float*)d_in[18];
    float* out = (float*)d_out;

    float *p_cat, *p_pre1, *p_h, *p_mid, *p_moe, *p_probs, *p_w1t, *p_w2t;
    cudaGetSymbolAddress((void**)&p_cat,   g_cat);
    cudaGetSymbolAddress((void**)&p_pre1,  g_pre1);
    cudaGetSymbolAddress((void**)&p_h,     g_h);
    cudaGetSymbolAddress((void**)&p_mid,   g_mid);
    cudaGetSymbolAddress((void**)&p_moe,   g_moe);
    cudaGetSymbolAddress((void**)&p_probs, g_probs);
    cudaGetSymbolAddress((void**)&p_w1t,   g_w1t);
    cudaGetSymbolAddress((void**)&p_w2t,   g_w2t);

    cudaFuncSetAttribute(attn_kernel,
                         cudaFuncAttributeMaxDynamicSharedMemorySize, ATTN_SMEM);
    cudaFuncSetAttribute(mm_gemm<1>,
                         cudaFuncAttributeMaxDynamicSharedMemorySize, MM_SMEM);
    cudaFuncSetAttribute(mm_gemm<2>,
                         cudaFuncAttributeMaxDynamicSharedMemorySize, MM_SMEM);

    // weight transposes + tf32 rounding
    transpose_rna<<<dim3(FF_ / 32, E_ / 32, NE_), dim3(32, 8)>>>(
        w1, p_w1t, FF_, (long)E_, (long)E_ * FF_, (long)FF_ * E_);
    transpose_rna<<<dim3(E_ / 32, FF_ / 32, NE_), dim3(32, 8)>>>(
        w2, p_w2t, E_, (long)NFF_, (long)FF_ * E_, (long)FF_);

    // attention path
    qkv_kernel<<<dim3(T_ / 64, H_), 256>>>(x, wq, bq, wk, bk, wv, bv);
    attn_kernel<<<dim3(S_ / 64, B_ * H_), 256, ATTN_SMEM>>>();
    proj_kernel<<<dim3(E_ / 128, T_ / 128), 256>>>(
        p_cat, wp, p_pre1, T_, E_, E_, bp, x);
    ln_kernel<true><<<T_, 256>>>(p_pre1, ln1g, ln1b, p_h, x, wr, br, b2);

    // MoE: per-expert GEMM pairs; mid (64MB) stays hot in L2 between the
    // producing GEMM1_n and consuming GEMM2_n. GEMM2 accumulates into
    // g_pre1 (base = g_moe for n=0, base aliases C for n>0).
    for (int n = 0; n < NE_; n++) {
        mm_gemm<1><<<dim3(FF_ / 128, T_ / 128), 256, MM_SMEM>>>(
            p_h, p_w1t + (size_t)n * FF_ * E_, p_mid, E_, E_,
            b1 + (size_t)n * FF_, p_probs, nullptr, n);
        mm_gemm<2><<<dim3(E_ / 128, T_ / 128), 256, MM_SMEM>>>(
            p_mid, p_w2t + (size_t)n * FF_, p_pre1, FF_, NFF_,
            nullptr, nullptr, (n == 0 ? p_moe : p_pre1), n);
    }

    ln_kernel<false><<<T_, 256>>>(p_pre1, ln2g, ln2b, out, nullptr, nullptr, nullptr, nullptr);
}

// round 7
// speedup vs baseline: 1.7946x; 1.7946x over previous
#include <cuda_runtime.h>
#include <cuda_bf16.h>
#include <cstdint>

// ---------------- problem constants ----------------
constexpr int B_  = 4;
constexpr int S_  = 1024;
constexpr int E_  = 1024;
constexpr int H_  = 16;
constexpr int HD_ = 64;
constexpr int NE_ = 8;
constexpr int FF_ = 4096;
constexpr int T_  = B_ * S_;   // 4096 tokens
constexpr int NFF_ = NE_ * FF_; // 32768

// ---------------- device scratch ----------------
__device__ float g_q  [(size_t)B_ * H_ * S_ * HD_];
__device__ float g_k  [(size_t)B_ * H_ * S_ * HD_];
__device__ float g_v  [(size_t)B_ * H_ * S_ * HD_];
__device__ float g_cat[(size_t)T_ * E_];
__device__ float g_pre1[(size_t)T_ * E_];             // proj+resid, later GEMM2 out
__device__ float g_probs[(size_t)T_ * NE_];
__device__ float g_moe[(size_t)T_ * E_];              // x + sum_n probs*b2
__device__ __nv_bfloat16 g_hb  [(size_t)T_ * E_];     // LN1 out, bf16
__device__ __nv_bfloat16 g_w1b [(size_t)NFF_ * E_];   // [32768,1024] K-major bf16
__device__ __nv_bfloat16 g_w2b [(size_t)E_ * NFF_];   // [1024,32768] K-major bf16
__device__ __nv_bfloat16 g_midb[(size_t)T_ * NFF_];   // [4096,32768] bf16

// ---------------- helpers ----------------
#define CP_ASYNC16(dst, src) \
    asm volatile("cp.async.cg.shared.global [%0], [%1], 16;" :: "r"(dst), "l"(src) : "memory")
#define CP_COMMIT() asm volatile("cp.async.commit_group;" ::: "memory")
#define CP_WAIT2()  asm volatile("cp.async.wait_group 2;" ::: "memory")

__device__ __forceinline__ uint32_t smem_u32(const void* p) {
    uint32_t a;
    asm("{ .reg .u64 t; cvta.to.shared.u64 t, %1; cvt.u32.u64 %0, t; }"
        : "=r"(a) : "l"(p));
    return a;
}

__device__ __forceinline__ void mma_bf16(float* c, const uint32_t* a, const uint32_t* b) {
    asm volatile(
        "mma.sync.aligned.m16n8k16.row.col.f32.bf16.bf16.f32 "
        "{%0,%1,%2,%3}, {%4,%5,%6,%7}, {%8,%9}, {%0,%1,%2,%3};"
        : "+f"(c[0]), "+f"(c[1]), "+f"(c[2]), "+f"(c[3])
        : "r"(a[0]), "r"(a[1]), "r"(a[2]), "r"(a[3]), "r"(b[0]), "r"(b[1]));
}

// =====================================================================
// bf16 mma.sync GEMM: D[M,N] = A[M,K] @ B[N,:K]^T, bf16 K-major operands.
// CTA 128x128, 8 warps (2x4), warp tile 64x32 (4x4 m16n8k16), BK=32,
// 4-stage cp.async pipeline. Row stride in smem: 20 words (16 data + 4 pad)
// -> conflict-free scalar fragment loads (same proof as tf32 version).
// MODE 1: C(bf16) = bf16(relu(acc + bias[col]) * probs[row, col/4096])
// MODE 2: C(f32)  = acc + base[row,col]
// =====================================================================
constexpr int MM_LDA   = 20;                 // words per BK=32-half row
constexpr int MM_OPB   = 128 * MM_LDA * 4;   // bytes per operand stage = 10240
constexpr int MM_STG   = 4;
constexpr int MM_SMEM  = MM_STG * 2 * MM_OPB;  // 81920 bytes

template<int MODE>
__global__ __launch_bounds__(256, 1) void mm_gemm(
    const __nv_bfloat16* __restrict__ A, const __nv_bfloat16* __restrict__ Bm,
    void* __restrict__ Cv, int K, int ldb,
    const float* __restrict__ bias, const float* __restrict__ probs,
    const float* __restrict__ base)
{
    extern __shared__ __align__(16) float sm[];
    const uint32_t sbase = smem_u32(sm);
    const int tid = threadIdx.x, wid = tid >> 5, lane = tid & 31;
    const int row0 = blockIdx.y * 128, col0 = blockIdx.x * 128;
    const int ldC = gridDim.x * 128;
    const int wm = wid & 1, wn = wid >> 1;
    const int nch = K >> 5;                  // BK = 32 halves

    // 4 cp.async 16B slots per thread per stage (2 A + 2 B)
    const __nv_bfloat16* gsrc[4];
    uint32_t doff[4];
    #pragma unroll
    for (int i = 0; i < 4; i++) {
        int id = tid + i * 256;              // 0..1023
        bool isB = id >= 512;
        int r = (id & 511) >> 2;             // row 0..127
        int kc = id & 3;                     // 16B chunk within 64B row
        gsrc[i] = (isB ? Bm + (size_t)(col0 + r) * ldb
                       : A  + (size_t)(row0 + r) * K) + kc * 8;
        doff[i] = (isB ? MM_OPB : 0) + r * 80 + kc * 16;
    }

    float acc[4][4][4] = {};

    #pragma unroll
    for (int c = 0; c < MM_STG - 1; c++) {
        uint32_t so = sbase + c * 2 * MM_OPB;
        int ko = c * 32;
        #pragma unroll
        for (int i = 0; i < 4; i++) CP_ASYNC16(so + doff[i], gsrc[i] + ko);
        CP_COMMIT();
    }

    const int lr = lane >> 2, lc = lane & 3;
    for (int c = 0; c < nch; c++) {
        CP_WAIT2();
        __syncthreads();
        if (c + MM_STG - 1 < nch) {
            int s = (c + MM_STG - 1) & (MM_STG - 1);
            uint32_t so = sbase + s * 2 * MM_OPB;
            int ko = (c + MM_STG - 1) * 32;
            #pragma unroll
            for (int i = 0; i < 4; i++) CP_ASYNC16(so + doff[i], gsrc[i] + ko);
        }
        CP_COMMIT();

        const uint32_t* Ast = (const uint32_t*)sm + (c & (MM_STG - 1)) * (2 * MM_OPB / 4);
        const uint32_t* Bst = Ast + MM_OPB / 4;
        #pragma unroll
        for (int ko = 0; ko < 16; ko += 8) {   // two k16 steps per BK=32
            uint32_t af[4][4], bf[4][2];
            #pragma unroll
            for (int mt = 0; mt < 4; mt++) {
                int ba = (wm * 64 + mt * 16 + lr) * MM_LDA + ko + lc;
                af[mt][0] = Ast[ba];
                af[mt][1] = Ast[ba + 8 * MM_LDA];
                af[mt][2] = Ast[ba + 4];
                af[mt][3] = Ast[ba + 8 * MM_LDA + 4];
            }
            #pragma unroll
            for (int nt = 0; nt < 4; nt++) {
                int bb = (wn * 32 + nt * 8 + lr) * MM_LDA + ko + lc;
                bf[nt][0] = Bst[bb];
                bf[nt][1] = Bst[bb + 4];
            }
            #pragma unroll
            for (int mt = 0; mt < 4; mt++)
                #pragma unroll
                for (int nt = 0; nt < 4; nt++)
                    mma_bf16(acc[mt][nt], af[mt], bf[nt]);
        }
    }

    // epilogue
    #pragma unroll
    for (int mt = 0; mt < 4; mt++) {
        int r1 = row0 + wm * 64 + mt * 16 + lr;
        int r2 = r1 + 8;
        float p1 = 0.f, p2 = 0.f;
        if (MODE == 1) {
            int expert = col0 >> 12;
            p1 = probs[(size_t)r1 * NE_ + expert];
            p2 = probs[(size_t)r2 * NE_ + expert];
        }
        #pragma unroll
        for (int nt = 0; nt < 4; nt++) {
            int cg = col0 + wn * 32 + nt * 8 + lc * 2;
            if (MODE == 1) {
                __nv_bfloat16* C = (__nv_bfloat16*)Cv;
                float b0 = bias[cg], b1 = bias[cg + 1];
                __nv_bfloat162 v1, v2;
                v1.x = __float2bfloat16_rn(fmaxf(acc[mt][nt][0] + b0, 0.f) * p1);
                v1.y = __float2bfloat16_rn(fmaxf(acc[mt][nt][1] + b1, 0.f) * p1);
                v2.x = __float2bfloat16_rn(fmaxf(acc[mt][nt][2] + b0, 0.f) * p2);
                v2.y = __float2bfloat16_rn(fmaxf(acc[mt][nt][3] + b1, 0.f) * p2);
                *(__nv_bfloat162*)&C[(size_t)r1 * ldC + cg] = v1;
                *(__nv_bfloat162*)&C[(size_t)r2 * ldC + cg] = v2;
            } else {
                float* C = (float*)Cv;
                float2 a1 = *(const float2*)&base[(size_t)r1 * ldC + cg];
                float2 a2 = *(const float2*)&base[(size_t)r2 * ldC + cg];
                float2 v1 = make_float2(acc[mt][nt][0] + a1.x, acc[mt][nt][1] + a1.y);
                float2 v2 = make_float2(acc[mt][nt][2] + a2.x, acc[mt][nt][3] + a2.y);
                *(float2*)&C[(size_t)r1 * ldC + cg] = v1;
                *(float2*)&C[(size_t)r2 * ldC + cg] = v2;
            }
        }
    }
}

// ---------------- transpose + bf16-round weights ----------------
__global__ __launch_bounds__(256) void transpose_bf16(
    const float* __restrict__ src, __nv_bfloat16* __restrict__ dst,
    int srcStride, long dstStride, long srcExp, long dstExp)
{
    __shared__ float t[32][33];
    src += (size_t)blockIdx.z * srcExp;
    dst += (size_t)blockIdx.z * dstExp;
    const int r0 = blockIdx.y * 32, c0 = blockIdx.x * 32;
    const int tx = threadIdx.x, ty = threadIdx.y;
    #pragma unroll
    for (int i = 0; i < 4; i++)
        t[ty + i * 8][tx] = src[(size_t)(r0 + ty + i * 8) * srcStride + c0 + tx];
    __syncthreads();
    #pragma unroll
    for (int i = 0; i < 4; i++)
        dst[(size_t)(c0 + ty + i * 8) * dstStride + (r0 + tx)] =
            __float2bfloat16_rn(t[tx][ty + i * 8]);
}

// =====================================================================
// QKV projection (fp32)
// =====================================================================
__global__ __launch_bounds__(256) void qkv_kernel(
    const float* __restrict__ x,
    const float* __restrict__ wq, const float* __restrict__ bq,
    const float* __restrict__ wk, const float* __restrict__ bk,
    const float* __restrict__ wv, const float* __restrict__ bv)
{
    __shared__ float xs[16][68];
    __shared__ float ws[3][16][64];
    const int h  = blockIdx.y;
    const int t0 = blockIdx.x * 64;
    const int tid = threadIdx.x;
    const int tx = tid & 15, ty = tid >> 4;

    float acc[3][4][4] = {};
    const int xr = tid >> 2, xc = (tid & 3) * 4;
    const int wrow = tid >> 4, wcol = (tid & 15) * 4;
    const float* wqh = wq + (size_t)h * E_ * HD_;
    const float* wkh = wk + (size_t)h * E_ * HD_;
    const float* wvh = wv + (size_t)h * E_ * HD_;

    for (int k0 = 0; k0 < E_; k0 += 16) {
        float4 xv = *(const float4*)&x[(size_t)(t0 + xr) * E_ + k0 + xc];
        float4 q4 = *(const float4*)&wqh[(size_t)(k0 + wrow) * HD_ + wcol];
        float4 k4 = *(const float4*)&wkh[(size_t)(k0 + wrow) * HD_ + wcol];
        float4 v4 = *(const float4*)&wvh[(size_t)(k0 + wrow) * HD_ + wcol];
        __syncthreads();
        xs[xc + 0][xr] = xv.x; xs[xc + 1][xr] = xv.y;
        xs[xc + 2][xr] = xv.z; xs[xc + 3][xr] = xv.w;
        *(float4*)&ws[0][wrow][wcol] = q4;
        *(float4*)&ws[1][wrow][wcol] = k4;
        *(float4*)&ws[2][wrow][wcol] = v4;
        __syncthreads();
        #pragma unroll
        for (int kk = 0; kk < 16; kk++) {
            float4 a4 = *(const float4*)&xs[kk][ty * 4];
            float a[4] = {a4.x, a4.y, a4.z, a4.w};
            float4 qb4 = *(const float4*)&ws[0][kk][tx * 4];
            float4 kb4 = *(const float4*)&ws[1][kk][tx * 4];
            float4 vb4 = *(const float4*)&ws[2][kk][tx * 4];
            float qv[4] = {qb4.x, qb4.y, qb4.z, qb4.w};
            float kv[4] = {kb4.x, kb4.y, kb4.z, kb4.w};
            float vv[4] = {vb4.x, vb4.y, vb4.z, vb4.w};
            #pragma unroll
            for (int i = 0; i < 4; i++)
                #pragma unroll
                for (int j = 0; j < 4; j++) {
                    acc[0][i][j] += a[i] * qv[j];
                    acc[1][i][j] += a[i] * kv[j];
                    acc[2][i][j] += a[i] * vv[j];
                }
        }
    }
    #pragma unroll
    for (int i = 0; i < 4; i++) {
        int t = t0 + ty * 4 + i;
        int b = t / S_, s = t % S_;
        size_t bs = ((size_t)(b * H_ + h) * S_ + s) * HD_;
        #pragma unroll
        for (int j = 0; j < 4; j++) {
            int d = tx * 4 + j;
            g_q[bs + d] = acc[0][i][j] + bq[h * HD_ + d];
            g_k[bs + d] = acc[1][i][j] + bk[h * HD_ + d];
            g_v[bs + d] = acc[2][i][j] + bv[h * HD_ + d];
        }
    }
}

// =====================================================================
// flash attention (fp32)
// =====================================================================
constexpr int AP = 68;
constexpr int ATTN_SMEM = 4 * 64 * AP * 4;

__global__ __launch_bounds__(256) void attn_kernel()
{
    extern __shared__ float asmem[];
    float* qs = asmem;
    float* ks = asmem + 64 * AP;
    float* vs = asmem + 2 * 64 * AP;
    float* ps = asmem + 3 * 64 * AP;

    const int qb = blockIdx.x;
    const int bh = blockIdx.y;
    const int b = bh / H_, h = bh % H_;
    const int q0 = qb * 64;
    const float* Q = g_q + (size_t)bh * S_ * HD_;
    const float* K = g_k + (size_t)bh * S_ * HD_;
    const float* V = g_v + (size_t)bh * S_ * HD_;

    const int tid = threadIdx.x;
    const int tx = tid & 15, ty = tid >> 4;
    const int lr = tid >> 2, lc = (tid & 3) * 16;

    #pragma unroll
    for (int ii = 0; ii < 4; ii++) {
        float4 qv = *(const float4*)&Q[(size_t)(q0 + lr) * HD_ + lc + ii * 4];
        *(float4*)&qs[lr * AP + lc + ii * 4] = qv;
    }

    float o[4][4] = {};
    float m[4], l[4];
    #pragma unroll
    for (int i = 0; i < 4; i++) { m[i] = -1e30f; l[i] = 0.f; }

    for (int jb = 0; jb <= qb; jb++) {
        const int kv0 = jb * 64;
        float4 kl[4], vl[4];
        #pragma unroll
        for (int ii = 0; ii < 4; ii++) {
            kl[ii] = *(const float4*)&K[(size_t)(kv0 + lr) * HD_ + lc + ii * 4];
            vl[ii] = *(const float4*)&V[(size_t)(kv0 + lr) * HD_ + lc + ii * 4];
        }
        __syncthreads();
        #pragma unroll
        for (int ii = 0; ii < 4; ii++) {
            *(float4*)&ks[lr * AP + lc + ii * 4] = kl[ii];
            *(float4*)&vs[lr * AP + lc + ii * 4] = vl[ii];
        }
        __syncthreads();

        float s[4][4] = {};
        #pragma unroll
        for (int d = 0; d < 64; d += 4) {
            float4 a4[4], b4[4];
            #pragma unroll
            for (int i = 0; i < 4; i++)
                a4[i] = *(const float4*)&qs[(ty * 4 + i) * AP + d];
            #pragma unroll
            for (int j = 0; j < 4; j++)
                b4[j] = *(const float4*)&ks[(tx * 4 + j) * AP + d];
            #pragma unroll
            for (int i = 0; i < 4; i++)
                #pragma unroll
                for (int j = 0; j < 4; j++)
                    s[i][j] += a4[i].x * b4[j].x + a4[i].y * b4[j].y
                             + a4[i].z * b4[j].z + a4[i].w * b4[j].w;
        }
        #pragma unroll
        for (int i = 0; i < 4; i++)
            #pragma unroll
            for (int j = 0; j < 4; j++) {
                s[i][j] *= 0.125f;
                if (kv0 + tx * 4 + j > q0 + ty * 4 + i) s[i][j] = -1e30f;
            }

        float corr[4];
        #pragma unroll
        for (int i = 0; i < 4; i++) {
            float mloc = fmaxf(fmaxf(s[i][0], s[i][1]), fmaxf(s[i][2], s[i][3]));
            #pragma unroll
            for (int off = 8; off; off >>= 1)
                mloc = fmaxf(mloc, __shfl_xor_sync(0xffffffffu, mloc, off));
            float mnew = fmaxf(m[i], mloc);
            corr[i] = __expf(fmaxf(m[i] - mnew, -87.f));
            float4 p;
            p.x = __expf(fmaxf(s[i][0] - mnew, -87.f));
            p.y = __expf(fmaxf(s[i][1] - mnew, -87.f));
            p.z = __expf(fmaxf(s[i][2] - mnew, -87.f));
            p.w = __expf(fmaxf(s[i][3] - mnew, -87.f));
            *(float4*)&ps[(ty * 4 + i) * AP + tx * 4] = p;
            float psum = p.x + p.y + p.z + p.w;
            #pragma unroll
            for (int off = 8; off; off >>= 1)
                psum += __shfl_xor_sync(0xffffffffu, psum, off);
            l[i] = l[i] * corr[i] + psum;
            m[i] = mnew;
        }
        __syncwarp();

        #pragma unroll
        for (int i = 0; i < 4; i++)
            #pragma unroll
            for (int j = 0; j < 4; j++)
                o[i][j] *= corr[i];
        #pragma unroll
        for (int c = 0; c < 64; c += 4) {
            float4 p4[4], v4[4];
            #pragma unroll
            for (int i = 0; i < 4; i++)
                p4[i] = *(const float4*)&ps[(ty * 4 + i) * AP + c];
            #pragma unroll
            for (int cc = 0; cc < 4; cc++)
                v4[cc] = *(const float4*)&vs[(c + cc) * AP + tx * 4];
            #pragma unroll
            for (int i = 0; i < 4; i++) {
                o[i][0] += p4[i].x * v4[0].x + p4[i].y * v4[1].x + p4[i].z * v4[2].x + p4[i].w * v4[3].x;
                o[i][1] += p4[i].x * v4[0].y + p4[i].y * v4[1].y + p4[i].z * v4[2].y + p4[i].w * v4[3].y;
                o[i][2] += p4[i].x * v4[0].z + p4[i].y * v4[1].z + p4[i].z * v4[2].z + p4[i].w * v4[3].z;
                o[i][3] += p4[i].x * v4[0].w + p4[i].y * v4[1].w + p4[i].z * v4[2].w + p4[i].w * v4[3].w;
            }
        }
    }
    #pragma unroll
    for (int i = 0; i < 4; i++) {
        float inv = 1.f / l[i];
        int srow = q0 + ty * 4 + i;
        float4 ov = make_float4(o[i][0] * inv, o[i][1] * inv, o[i][2] * inv, o[i][3] * inv);
        *(float4*)&g_cat[((size_t)b * S_ + srow) * E_ + h * HD_ + tx * 4] = ov;
    }
}

// =====================================================================
// fp32 SGEMM — attention projection: C = A@B + bias[col] + resid[row,col]
// =====================================================================
__global__ __launch_bounds__(256) void proj_kernel(
    const float* __restrict__ A, const float* __restrict__ Bm,
    float* __restrict__ C, int M, int N, int K,
    const float* __restrict__ bias, const float* __restrict__ resid)
{
    __shared__ float As[8][128];
    __shared__ float Bs[8][128];
    const int tid = threadIdx.x;
    const int tx = tid & 15, ty = tid >> 4;
    const int row0 = blockIdx.y * 128, col0 = blockIdx.x * 128;

    float acc[8][8] = {};
    const int arow = tid >> 1, acol = (tid & 1) * 4;
    const int brow = tid >> 5, bcol = (tid & 31) * 4;

    for (int k0 = 0; k0 < K; k0 += 8) {
        float4 av = *(const float4*)&A[(size_t)(row0 + arow) * K + k0 + acol];
        float4 bv = *(const float4*)&Bm[(size_t)(k0 + brow) * N + col0 + bcol];
        __syncthreads();
        As[acol + 0][arow] = av.x; As[acol + 1][arow] = av.y;
        As[acol + 2][arow] = av.z; As[acol + 3][arow] = av.w;
        *(float4*)&Bs[brow][bcol] = bv;
        __syncthreads();
        #pragma unroll
        for (int kk = 0; kk < 8; kk++) {
            float4 a0 = *(const float4*)&As[kk][ty * 4];
            float4 a1 = *(const float4*)&As[kk][64 + ty * 4];
            float4 b0 = *(const float4*)&Bs[kk][tx * 4];
            float4 b1 = *(const float4*)&Bs[kk][64 + tx * 4];
            float ar[8] = {a0.x, a0.y, a0.z, a0.w, a1.x, a1.y, a1.z, a1.w};
            float br_[8] = {b0.x, b0.y, b0.z, b0.w, b1.x, b1.y, b1.z, b1.w};
            #pragma unroll
            for (int i = 0; i < 8; i++)
                #pragma unroll
                for (int j = 0; j < 8; j++)
                    acc[i][j] += ar[i] * br_[j];
        }
    }
    #pragma unroll
    for (int i = 0; i < 8; i++) {
        int row = row0 + (i < 4 ? ty * 4 + i : 64 + ty * 4 + (i - 4));
        #pragma unroll
        for (int j = 0; j < 8; j++) {
            int col = col0 + (j < 4 ? tx * 4 + j : 64 + tx * 4 + (j - 4));
            size_t ci = (size_t)row * N + col;
            C[ci] = acc[i][j] + bias[col] + resid[ci];
        }
    }
}

// =====================================================================
// LayerNorm. FIRST: writes bf16 h, router probs, and residual base
// g_moe = x + sum_n probs[n]*b2[n]. !FIRST: fp32 out.
// =====================================================================
template<bool FIRST>
__global__ __launch_bounds__(256) void ln_kernel(
    const float* __restrict__ src, const float* __restrict__ gamma,
    const float* __restrict__ beta, void* __restrict__ dstv,
    const float* __restrict__ x, const float* __restrict__ wr,
    const float* __restrict__ br, const float* __restrict__ b2)
{
    const int t = blockIdx.x, tid = threadIdx.x;
    const size_t rb = (size_t)t * E_;
    float4 v = *(const float4*)&src[rb + tid * 4];
    float sum = v.x + v.y + v.z + v.w;
    float sq  = v.x * v.x + v.y * v.y + v.z * v.z + v.w * v.w;

    __shared__ float red[16];
    const int lane = tid & 31, w = tid >> 5;
    #pragma unroll
    for (int off = 16; off; off >>= 1) {
        sum += __shfl_down_sync(0xffffffffu, sum, off);
        sq  += __shfl_down_sync(0xffffffffu, sq, off);
    }
    if (lane == 0) { red[w] = sum; red[8 + w] = sq; }
    __syncthreads();
    if (tid == 0) {
        float S = 0.f, Q = 0.f;
        for (int i = 0; i < 8; i++) { S += red[i]; Q += red[8 + i]; }
        float mean = S * (1.f / E_);
        float var  = Q * (1.f / E_) - mean * mean;
        red[0] = mean; red[1] = rsqrtf(var + 1e-5f);
    }
    __syncthreads();
    float mean = red[0], inv = red[1];

    float hv[4];
    hv[0] = (v.x - mean) * inv * gamma[tid * 4 + 0] + beta[tid * 4 + 0];
    hv[1] = (v.y - mean) * inv * gamma[tid * 4 + 1] + beta[tid * 4 + 1];
    hv[2] = (v.z - mean) * inv * gamma[tid * 4 + 2] + beta[tid * 4 + 2];
    hv[3] = (v.w - mean) * inv * gamma[tid * 4 + 3] + beta[tid * 4 + 3];
    if (FIRST) {
        __nv_bfloat16* dst = (__nv_bfloat16*)dstv;
        __nv_bfloat162 h0, h1;
        h0.x = __float2bfloat16_rn(hv[0]); h0.y = __float2bfloat16_rn(hv[1]);
        h1.x = __float2bfloat16_rn(hv[2]); h1.y = __float2bfloat16_rn(hv[3]);
        *(__nv_bfloat162*)&dst[rb + tid * 4]     = h0;
        *(__nv_bfloat162*)&dst[rb + tid * 4 + 2] = h1;
    } else {
        float* dst = (float*)dstv;
        *(float4*)&dst[rb + tid * 4] = make_float4(hv[0], hv[1], hv[2], hv[3]);
    }

    if (FIRST) {
        __shared__ float slog[8];
        float lg[8] = {};
        #pragma unroll
        for (int i = 0; i < 4; i++) {
            int e = tid * 4 + i;
            #pragma unroll
            for (int n = 0; n < 8; n++) lg[n] += hv[i] * wr[e * 8 + n];
        }
        if (tid < 8) slog[tid] = 0.f;
        __syncthreads();
        #pragma unroll
        for (int n = 0; n < 8; n++) {
            float vv = lg[n];
            #pragma unroll
            for (int off = 16; off; off >>= 1)
                vv += __shfl_down_sync(0xffffffffu, vv, off);
            if (lane == 0) atomicAdd(&slog[n], vv);
        }
        __syncthreads();
        if (tid == 0) {
            float lgf[8], mx = -1e30f;
            for (int n = 0; n < 8; n++) { lgf[n] = slog[n] + br[n]; mx = fmaxf(mx, lgf[n]); }
            float sme = 0.f, ee[8];
            for (int n = 0; n < 8; n++) { ee[n] = __expf(lgf[n] - mx); sme += ee[n]; }
            float is = 1.f / sme;
            for (int n = 0; n < 8; n++) {
                float p = ee[n] * is;
                g_probs[(size_t)t * 8 + n] = p;
                slog[n] = p;
            }
        }
        __syncthreads();
        float4 xv = *(const float4*)&x[rb + tid * 4];
        float bb[4] = {xv.x, xv.y, xv.z, xv.w};
        #pragma unroll
        for (int n = 0; n < 8; n++) {
            float p = slog[n];
            #pragma unroll
            for (int i = 0; i < 4; i++)
                bb[i] += p * b2[n * E_ + tid * 4 + i];
        }
        *(float4*)&g_moe[rb + tid * 4] = make_float4(bb[0], bb[1], bb[2], bb[3]);
    }
}

// =====================================================================
// host launcher
// =====================================================================
extern "C" void kernel_launch(void* const* d_in, const int* in_sizes, int n_in,
                              void* d_out, int out_size)
{
    const float* x    = (const float*)d_in[0];
    const float* wq   = (const float*)d_in[1];
    const float* bq   = (const float*)d_in[2];
    const float* wk   = (const float*)d_in[3];
    const float* bk   = (const float*)d_in[4];
    const float* wv   = (const float*)d_in[5];
    const float* bv   = (const float*)d_in[6];
    const float* wp   = (const float*)d_in[7];
    const float* bp   = (const float*)d_in[8];
    const float* ln1g = (const float*)d_in[9];
    const float* ln1b = (const float*)d_in[10];
    const float* ln2g = (const float*)d_in[11];
    const float* ln2b = (const float*)d_in[12];
    const float* wr   = (const float*)d_in[13];
    const float* br   = (const float*)d_in[14];
    const float* w1   = (const float*)d_in[15];
    const float* b1   = (const float*)d_in[16];
    const float* w2   = (const float*)d_in[17];
    const float* b2   = (const float*)d_in[18];
    float* out = (float*)d_out;

    float *p_cat, *p_pre1, *p_moe, *p_probs;
    __nv_bfloat16 *p_hb, *p_w1b, *p_w2b, *p_midb;
    cudaGetSymbolAddress((void**)&p_cat,   g_cat);
    cudaGetSymbolAddress((void**)&p_pre1,  g_pre1);
    cudaGetSymbolAddress((void**)&p_moe,   g_moe);
    cudaGetSymbolAddress((void**)&p_probs, g_probs);
    cudaGetSymbolAddress((void**)&p_hb,    g_hb);
    cudaGetSymbolAddress((void**)&p_w1b,   g_w1b);
    cudaGetSymbolAddress((void**)&p_w2b,   g_w2b);
    cudaGetSymbolAddress((void**)&p_midb,  g_midb);

    cudaFuncSetAttribute(attn_kernel,
                         cudaFuncAttributeMaxDynamicSharedMemorySize, ATTN_SMEM);
    cudaFuncSetAttribute(mm_gemm<1>,
                         cudaFuncAttributeMaxDynamicSharedMemorySize, MM_SMEM);
    cudaFuncSetAttribute(mm_gemm<2>,
                         cudaFuncAttributeMaxDynamicSharedMemorySize, MM_SMEM);

    // weight transposes + bf16 rounding
    transpose_bf16<<<dim3(FF_ / 32, E_ / 32, NE_), dim3(32, 8)>>>(
        w1, p_w1b, FF_, (long)E_, (long)E_ * FF_, (long)FF_ * E_);
    transpose_bf16<<<dim3(E_ / 32, FF_ / 32, NE_), dim3(32, 8)>>>(
        w2, p_w2b, E_, (long)NFF_, (long)FF_ * E_, (long)FF_);

    // attention path
    qkv_kernel<<<dim3(T_ / 64, H_), 256>>>(x, wq, bq, wk, bk, wv, bv);
    attn_kernel<<<dim3(S_ / 64, B_ * H_), 256, ATTN_SMEM>>>();
    proj_kernel<<<dim3(E_ / 128, T_ / 128), 256>>>(
        p_cat, wp, p_pre1, T_, E_, E_, bp, x);
    ln_kernel<true><<<T_, 256>>>(p_pre1, ln1g, ln1b, p_hb, x, wr, br, b2);

    // MoE as two big bf16 tensor-core GEMMs (fused experts along N / K)
    mm_gemm<1><<<dim3(NFF_ / 128, T_ / 128), 256, MM_SMEM>>>(
        p_hb, p_w1b, p_midb, E_, E_, b1, p_probs, nullptr);
    mm_gemm<2><<<dim3(E_ / 128, T_ / 128), 256, MM_SMEM>>>(
        p_midb, p_w2b, p_pre1, NFF_, NFF_, nullptr, nullptr, p_moe);

    ln_kernel<false><<<T_, 256>>>(p_pre1, ln2g, ln2b, out, nullptr, nullptr, nullptr, nullptr);
}